// round 2
// baseline (speedup 1.0000x reference)
#include <cuda_runtime.h>

#define C 32

// ---------------------------------------------------------------------------
// Kernel 1: initialize output with bias (d_out is poisoned to 0xAA by harness)
// out[v*32 + c] = bias[c]; vectorized float4 (channel quad = idx & 7)
// ---------------------------------------------------------------------------
__global__ void init_bias_kernel(float* __restrict__ out,
                                 const float* __restrict__ bias,
                                 int n4) {
    int idx = blockIdx.x * blockDim.x + threadIdx.x;
    if (idx < n4) {
        const float4* b4 = (const float4*)bias;
        ((float4*)out)[idx] = b4[idx & 7];
    }
}

// ---------------------------------------------------------------------------
// Kernel 2: gather -> per-offset GEMM -> scatter-add
//
// Pairs are grouped by kernel offset k (P pairs per offset). Each block is
// pinned to one k and loads W[k] (32x32 fp32 = 4KB) to smem.
//
// Warp layout: 4 pairs in flight per warp iteration.
//   lane = q*8 + t   (q = pair slot 0..3, t = channel quad 0..7)
// Input row of pair q is held across its 8 lanes as float4s; element i is
// broadcast with __shfl_sync(width=8). Each lane accumulates 4 output
// channels (float4 acc), scattered with one red.global.add.v4.f32.
// ---------------------------------------------------------------------------
__global__ __launch_bounds__(256) void spconv_kernel(
    const float* __restrict__ in_feature,
    const float* __restrict__ weights,
    const int2* __restrict__ nbmap,
    float* __restrict__ out,
    int P, int chunkPairs, int blocksPerSeg)
{
    __shared__ float Ws[C * C];

    int k = blockIdx.x / blocksPerSeg;
    int b = blockIdx.x % blocksPerSeg;

    for (int i = threadIdx.x; i < C * C; i += blockDim.x)
        Ws[i] = weights[k * C * C + i];
    __syncthreads();

    const float4* Ws4 = (const float4*)Ws;  // Ws4[i*8 + t] = W[k][i][4t..4t+3]

    int lane = threadIdx.x & 31;
    int warp = threadIdx.x >> 5;
    int t = lane & 7;   // channel quad
    int q = lane >> 3;  // pair slot within warp group

    int segStart   = k * P;
    int segEnd     = segStart + P;
    int chunkStart = segStart + b * chunkPairs;
    int chunkEnd   = min(chunkStart + chunkPairs, segEnd);

    // contiguous slice per warp (blockDim = 256 -> 8 warps)
    int perWarp = (chunkPairs + 7) >> 3;
    int wStart  = chunkStart + warp * perWarp;
    int wEnd    = min(wStart + perWarp, chunkEnd);

    for (int p0 = wStart; p0 < wEnd; p0 += 4) {
        int p = p0 + q;
        bool valid = (p < wEnd);
        int2 ij = valid ? nbmap[p] : make_int2(0, 0);

        // gather: 8 lanes of subgroup q each load one float4 of row ij.x
        const float4* row = (const float4*)(in_feature + (size_t)ij.x * C);
        float4 r = row[t];

        float4 acc = make_float4(0.f, 0.f, 0.f, 0.f);

        #pragma unroll
        for (int i = 0; i < C; i++) {
            float comp = ((i & 3) == 0) ? r.x :
                         ((i & 3) == 1) ? r.y :
                         ((i & 3) == 2) ? r.z : r.w;
            // broadcast element i of pair q's row within the 8-lane subgroup
            float a = __shfl_sync(0xffffffffu, comp, i >> 2, 8);
            float4 w = Ws4[i * 8 + t];
            acc.x = fmaf(a, w.x, acc.x);
            acc.y = fmaf(a, w.y, acc.y);
            acc.z = fmaf(a, w.z, acc.z);
            acc.w = fmaf(a, w.w, acc.w);
        }

        if (valid) {
            float* op = out + (size_t)ij.y * C + t * 4;
            asm volatile("red.global.add.v4.f32 [%0], {%1,%2,%3,%4};"
                         :: "l"(op), "f"(acc.x), "f"(acc.y), "f"(acc.z), "f"(acc.w)
                         : "memory");
        }
    }
}

// ---------------------------------------------------------------------------
// Inputs (metadata order):
//   0: in_feature f32 [N_VOX, 32]
//   1: kernel     f32 [K3, 32, 32]
//   2: bias       f32 [32]
//   3: nbmap      i32 [M, 2]
//   4: nbsizes    i32 [K3]   (equal segments; reference ignores it -> we do too)
// ---------------------------------------------------------------------------
extern "C" void kernel_launch(void* const* d_in, const int* in_sizes, int n_in,
                              void* d_out, int out_size) {
    const float* in_feature = (const float*)d_in[0];
    const float* weights    = (const float*)d_in[1];
    const float* bias       = (const float*)d_in[2];
    const int2*  nbmap      = (const int2*)d_in[3];
    float*       out        = (float*)d_out;

    int M  = in_sizes[3] / 2;
    int K3 = in_sizes[1] / (C * C);
    int P  = M / K3;

    // init output with bias
    int n4 = out_size / 4;
    init_bias_kernel<<<(n4 + 255) / 256, 256>>>(out, bias, n4);

    // main sparse-conv
    int chunkPairs   = 512;
    int blocksPerSeg = (P + chunkPairs - 1) / chunkPairs;
    spconv_kernel<<<K3 * blocksPerSeg, 256>>>(in_feature, weights, nbmap, out,
                                              P, chunkPairs, blocksPerSeg);
}

// round 5
// speedup vs baseline: 3.0507x; 3.0507x over previous
#include <cuda_runtime.h>
#include <cuda_bf16.h>
#include <cstdint>

#define C 32
#define WARPS 8
#define ROW_U32 20   // 80B padded row stride (32 bf16 data + 16B pad), conflict-free

// ---------------------------------------------------------------------------
// bf16 two-term split of a float2 -> (hi pair packed, lo pair packed)
// ---------------------------------------------------------------------------
static __device__ __forceinline__ uint2 split2(float x, float y) {
    __nv_bfloat162 h = __float22bfloat162_rn(make_float2(x, y));
    float hx = __bfloat162float(h.x);
    float hy = __bfloat162float(h.y);
    __nv_bfloat162 l = __float22bfloat162_rn(make_float2(x - hx, y - hy));
    uint2 r;
    r.x = *(uint32_t*)&h;   // hi: [y|x]
    r.y = *(uint32_t*)&l;   // lo
    return r;
}

static __device__ __forceinline__ void mma_bf16(float* d, const uint32_t* a,
                                                const uint32_t* b) {
    asm volatile(
        "mma.sync.aligned.m16n8k16.row.col.f32.bf16.bf16.f32 "
        "{%0,%1,%2,%3}, {%4,%5,%6,%7}, {%8,%9}, {%0,%1,%2,%3};"
        : "+f"(d[0]), "+f"(d[1]), "+f"(d[2]), "+f"(d[3])
        : "r"(a[0]), "r"(a[1]), "r"(a[2]), "r"(a[3]), "r"(b[0]), "r"(b[1]));
}

// ---------------------------------------------------------------------------
// Kernel 1: initialize output with bias
// ---------------------------------------------------------------------------
__global__ void init_bias_kernel(float* __restrict__ out,
                                 const float* __restrict__ bias, int n4) {
    int idx = blockIdx.x * blockDim.x + threadIdx.x;
    if (idx < n4) {
        const float4* b4 = (const float4*)bias;
        ((float4*)out)[idx] = b4[idx & 7];
    }
}

// ---------------------------------------------------------------------------
// Kernel 2: gather -> split-bf16 HMMA GEMM -> scatter-add
// Each warp: 32 pairs/iteration. A tiles staged in smem (hi/lo), B fragments
// register-resident per block (one kernel offset per block).
// ---------------------------------------------------------------------------
__global__ __launch_bounds__(256, 2) void spconv_hmma_kernel(
    const float* __restrict__ in_feature,
    const float* __restrict__ weights,
    const int2* __restrict__ nbmap,
    float* __restrict__ out,
    int P, int blocksPerSeg)
{
    // per-warp staging: [warp][hi/lo][32 rows * 20 u32]
    __shared__ uint32_t As[WARPS][2][32 * ROW_U32];

    const int tid  = threadIdx.x;
    const int wid  = tid >> 5;
    const int lane = tid & 31;
    const int l4   = lane >> 2;   // 0..7
    const int lm4  = lane & 3;    // 0..3
    const int t8   = lane & 7;    // chunk within row (gather)
    const int r8   = lane >> 3;   // subrow (gather)
    const bool odd = lane & 1;

    const int seg = blockIdx.x / blocksPerSeg;
    const int blk = blockIdx.x % blocksPerSeg;

    // ---- build register-resident B fragments (hi & lo) for this segment ----
    // B col-major frag m16n8k16: b0: k=(lm4)*2+{0,1}, n=l4 ; b1: k += 8
    const float* W = weights + seg * C * C;
    uint32_t Bh[4][2][2], Bl[4][2][2];
    #pragma unroll
    for (int n = 0; n < 4; n++) {
        #pragma unroll
        for (int kc = 0; kc < 2; kc++) {
            #pragma unroll
            for (int rr = 0; rr < 2; rr++) {
                int k0 = kc * 16 + lm4 * 2 + rr * 8;
                int ni = n * 8 + l4;
                float w0 = W[k0 * C + ni];
                float w1 = W[(k0 + 1) * C + ni];
                uint2 s = split2(w0, w1);
                Bh[n][kc][rr] = s.x;
                Bl[n][kc][rr] = s.y;
            }
        }
    }

    uint32_t* Ahw = &As[wid][0][0];
    uint32_t* Alw = &As[wid][1][0];

    // ---- per-warp contiguous pair range ----
    const int segStart = seg * P;
    const int segEnd   = segStart + P;
    const int warpsPerSeg = blocksPerSeg * WARPS;
    const int perWarp  = (P + warpsPerSeg - 1) / warpsPerSeg;
    int wStart = segStart + (blk * WARPS + wid) * perWarp;
    int wEnd   = min(wStart + perWarp, segEnd);

    for (int pBase = wStart; pBase < wEnd; pBase += 32) {
        const int vc = min(32, wEnd - pBase);

        // pair indices for this iteration
        int p = pBase + lane;
        int pc = min(p, segEnd - 1);
        int2 ij = nbmap[pc];
        int x_reg = ij.x;
        int y_reg = ij.y;

        // ---- gather + split + STS : 8 lanes per row, 4 rows per step ----
        #pragma unroll
        for (int g = 0; g < 8; g++) {
            int q = 4 * g + r8;
            int x = __shfl_sync(0xffffffffu, x_reg, q);
            float4 v = __ldg((const float4*)(in_feature + (size_t)x * C) + t8);
            uint2 s0 = split2(v.x, v.y);
            uint2 s1 = split2(v.z, v.w);
            uint2 hi = make_uint2(s0.x, s1.x);
            uint2 lo = make_uint2(s0.y, s1.y);
            *(uint2*)&Ahw[q * ROW_U32 + t8 * 2] = hi;
            *(uint2*)&Alw[q * ROW_U32 + t8 * 2] = lo;
        }
        __syncwarp();

        // ---- load A fragments (hi & lo), 2 m-tiles x 2 k-chunks ----
        uint32_t Ah[2][2][4], Al[2][2][4];
        #pragma unroll
        for (int m = 0; m < 2; m++) {
            #pragma unroll
            for (int kc = 0; kc < 2; kc++) {
                int b0 = (16 * m + l4) * ROW_U32 + kc * 8 + lm4;
                int b1 = b0 + 8 * ROW_U32;
                Ah[m][kc][0] = Ahw[b0];
                Ah[m][kc][1] = Ahw[b1];
                Ah[m][kc][2] = Ahw[b0 + 4];
                Ah[m][kc][3] = Ahw[b1 + 4];
                Al[m][kc][0] = Alw[b0];
                Al[m][kc][1] = Alw[b1];
                Al[m][kc][2] = Alw[b0 + 4];
                Al[m][kc][3] = Alw[b1 + 4];
            }
        }
        __syncwarp();

        // ---- per n-tile: MMA (3-term split) + epilogue scatter ----
        #pragma unroll
        for (int n = 0; n < 4; n++) {
            float d[2][4] = {{0.f, 0.f, 0.f, 0.f}, {0.f, 0.f, 0.f, 0.f}};
            #pragma unroll
            for (int m = 0; m < 2; m++) {
                #pragma unroll
                for (int kc = 0; kc < 2; kc++) {
                    mma_bf16(d[m], Ah[m][kc], Bh[n][kc]);
                    mma_bf16(d[m], Ah[m][kc], Bl[n][kc]);
                    mma_bf16(d[m], Al[m][kc], Bh[n][kc]);
                }
            }
            // epilogue: lane exchange (xor 1) to form channel quads, then red.v4
            #pragma unroll
            for (int m = 0; m < 2; m++) {
                uint32_t s0 = __float_as_uint(odd ? d[m][0] : d[m][2]);
                uint32_t s1 = __float_as_uint(odd ? d[m][1] : d[m][3]);
                uint32_t r0 = __shfl_xor_sync(0xffffffffu, s0, 1);
                uint32_t r1 = __shfl_xor_sync(0xffffffffu, s1, 1);
                float v0, v1, v2, v3;
                if (!odd) {
                    v0 = d[m][0]; v1 = d[m][1];
                    v2 = __uint_as_float(r0); v3 = __uint_as_float(r1);
                } else {
                    v0 = __uint_as_float(r0); v1 = __uint_as_float(r1);
                    v2 = d[m][2]; v3 = d[m][3];
                }
                int q = 16 * m + l4 + (odd ? 8 : 0);
                int y = __shfl_sync(0xffffffffu, y_reg, q);
                if (q < vc) {
                    float* op = out + (size_t)y * C + n * 8 + ((lm4 >= 2) ? 4 : 0);
                    asm volatile("red.global.add.v4.f32 [%0], {%1,%2,%3,%4};"
                                 :: "l"(op), "f"(v0), "f"(v1), "f"(v2), "f"(v3)
                                 : "memory");
                }
            }
        }
    }
}

// ---------------------------------------------------------------------------
// Inputs: 0 in_feature f32 [N_VOX,32], 1 kernel f32 [27,32,32], 2 bias f32[32],
//         3 nbmap i32 [M,2], 4 nbsizes i32 [27]
// ---------------------------------------------------------------------------
extern "C" void kernel_launch(void* const* d_in, const int* in_sizes, int n_in,
                              void* d_out, int out_size) {
    const float* in_feature = (const float*)d_in[0];
    const float* weights    = (const float*)d_in[1];
    const float* bias       = (const float*)d_in[2];
    const int2*  nbmap      = (const int2*)d_in[3];
    float*       out        = (float*)d_out;

    int M  = in_sizes[3] / 2;
    int K3 = in_sizes[1] / (C * C);
    int P  = M / K3;

    int n4 = out_size / 4;
    init_bias_kernel<<<(n4 + 255) / 256, 256>>>(out, bias, n4);

    int blocksPerSeg = 32;
    spconv_hmma_kernel<<<K3 * blocksPerSeg, 256>>>(
        in_feature, weights, nbmap, out, P, blocksPerSeg);
}

// round 6
// speedup vs baseline: 3.6766x; 1.2052x over previous
#include <cuda_runtime.h>
#include <cuda_bf16.h>
#include <cstdint>

#define C 32
#define WARPS 8
#define A_STRIDE 20          // words per A-staging row (80B, mostly conflict-free)
#define D_STRIDE 40          // words per D-staging row (160B, conflict-free both ways)
#define WARP_WORDS 1280      // 320 (A hi) + 320 (A lo) + 640 (D)

// ---------------------------------------------------------------------------
// bf16 two-term split of a float2 -> (hi pair packed, lo pair packed)
// ---------------------------------------------------------------------------
static __device__ __forceinline__ uint2 split2(float x, float y) {
    __nv_bfloat162 h = __float22bfloat162_rn(make_float2(x, y));
    float hx = __bfloat162float(h.x);
    float hy = __bfloat162float(h.y);
    __nv_bfloat162 l = __float22bfloat162_rn(make_float2(x - hx, y - hy));
    uint2 r;
    r.x = *(uint32_t*)&h;
    r.y = *(uint32_t*)&l;
    return r;
}

static __device__ __forceinline__ void mma_bf16(float* d, const uint32_t* a,
                                                const uint32_t* b) {
    asm volatile(
        "mma.sync.aligned.m16n8k16.row.col.f32.bf16.bf16.f32 "
        "{%0,%1,%2,%3}, {%4,%5,%6,%7}, {%8,%9}, {%0,%1,%2,%3};"
        : "+f"(d[0]), "+f"(d[1]), "+f"(d[2]), "+f"(d[3])
        : "r"(a[0]), "r"(a[1]), "r"(a[2]), "r"(a[3]), "r"(b[0]), "r"(b[1]));
}

// ---------------------------------------------------------------------------
// Kernel 1: initialize output with bias
// ---------------------------------------------------------------------------
__global__ void init_bias_kernel(float* __restrict__ out,
                                 const float* __restrict__ bias, int n4) {
    int idx = blockIdx.x * blockDim.x + threadIdx.x;
    if (idx < n4) {
        const float4* b4 = (const float4*)bias;
        ((float4*)out)[idx] = b4[idx & 7];
    }
}

// ---------------------------------------------------------------------------
// Kernel 2: gather -> split-bf16 HMMA -> smem-staged full-row scatter-add
// 16 pairs per warp-iteration (one m16 tile). D tile staged through smem so
// each red.global.add.v4 instruction covers 4 complete 128B output rows.
// ---------------------------------------------------------------------------
__global__ __launch_bounds__(256, 3) void spconv_hmma_kernel(
    const float* __restrict__ in_feature,
    const float* __restrict__ weights,
    const int2* __restrict__ nbmap,
    float* __restrict__ out,
    int P, int blocksPerSeg)
{
    __shared__ uint32_t S[WARPS][WARP_WORDS];

    const int tid  = threadIdx.x;
    const int wid  = tid >> 5;
    const int lane = tid & 31;
    const int l4   = lane >> 2;   // 0..7
    const int lm4  = lane & 3;    // 0..3
    const int t8   = lane & 7;    // 16B chunk within a 128B row
    const int r8   = lane >> 3;   // 0..3 subrow

    const int seg = blockIdx.x / blocksPerSeg;
    const int blk = blockIdx.x % blocksPerSeg;

    // ---- register-resident B fragments (hi & lo) for this segment ----
    const float* W = weights + seg * C * C;
    uint32_t Bh[4][2][2], Bl[4][2][2];
    #pragma unroll
    for (int n = 0; n < 4; n++) {
        #pragma unroll
        for (int kc = 0; kc < 2; kc++) {
            #pragma unroll
            for (int rr = 0; rr < 2; rr++) {
                int k0 = kc * 16 + lm4 * 2 + rr * 8;
                int ni = n * 8 + l4;
                float w0 = W[k0 * C + ni];
                float w1 = W[(k0 + 1) * C + ni];
                uint2 s = split2(w0, w1);
                Bh[n][kc][rr] = s.x;
                Bl[n][kc][rr] = s.y;
            }
        }
    }

    uint32_t* Ahw = S[wid];               // hi A staging: 16 rows * 20 words
    uint32_t* Alw = S[wid] + 320;         // lo A staging
    float*    Dw  = (float*)(S[wid] + 640); // D staging: 16 rows * 40 words

    // ---- per-warp contiguous pair range ----
    const int segStart = seg * P;
    const int segEnd   = segStart + P;
    const int warpsPerSeg = blocksPerSeg * WARPS;
    const int perWarp  = (P + warpsPerSeg - 1) / warpsPerSeg;
    int wStart = segStart + (blk * WARPS + wid) * perWarp;
    int wEnd   = min(wStart + perWarp, segEnd);

    for (int pBase = wStart; pBase < wEnd; pBase += 16) {
        const int vc = min(16, wEnd - pBase);

        // lanes 0..15 hold the 16 pair records
        int p  = pBase + lane;
        int pc = min(p, segEnd - 1);
        int2 ij = (lane < 16) ? nbmap[pc] : make_int2(0, 0);

        // ---- gather + split + STS A (8 lanes per row, 4 rows per step) ----
        #pragma unroll
        for (int g = 0; g < 4; g++) {
            int r = 4 * g + r8;
            int x = __shfl_sync(0xffffffffu, ij.x, r);
            float4 v = __ldg((const float4*)(in_feature + (size_t)x * C) + t8);
            uint2 s0 = split2(v.x, v.y);
            uint2 s1 = split2(v.z, v.w);
            *(uint2*)&Ahw[r * A_STRIDE + t8 * 2] = make_uint2(s0.x, s1.x);
            *(uint2*)&Alw[r * A_STRIDE + t8 * 2] = make_uint2(s0.y, s1.y);
        }
        __syncwarp();

        // ---- load A fragments (hi & lo), 2 k-chunks ----
        uint32_t Ah[2][4], Alr[2][4];
        #pragma unroll
        for (int kc = 0; kc < 2; kc++) {
            int b0 = l4 * A_STRIDE + kc * 8 + lm4;
            int b1 = b0 + 8 * A_STRIDE;
            Ah[kc][0] = Ahw[b0];
            Ah[kc][1] = Ahw[b1];
            Ah[kc][2] = Ahw[b0 + 4];
            Ah[kc][3] = Ahw[b1 + 4];
            Alr[kc][0] = Alw[b0];
            Alr[kc][1] = Alw[b1];
            Alr[kc][2] = Alw[b0 + 4];
            Alr[kc][3] = Alw[b1 + 4];
        }

        // ---- MMA (3-term split) + stage D rows into smem ----
        #pragma unroll
        for (int n = 0; n < 4; n++) {
            float d[4] = {0.f, 0.f, 0.f, 0.f};
            #pragma unroll
            for (int kc = 0; kc < 2; kc++) {
                mma_bf16(d, Ah[kc], Bh[n][kc]);
                mma_bf16(d, Ah[kc], Bl[n][kc]);
                mma_bf16(d, Alr[kc], Bh[n][kc]);
            }
            // d0,d1 -> row l4, cols 8n+2lm4.. ; d2,d3 -> row l4+8
            *(float2*)(Dw + l4 * D_STRIDE + n * 8 + lm4 * 2)       = make_float2(d[0], d[1]);
            *(float2*)(Dw + (l4 + 8) * D_STRIDE + n * 8 + lm4 * 2) = make_float2(d[2], d[3]);
        }
        __syncwarp();

        // ---- scatter: 4 red instructions, each = 4 complete 128B rows ----
        #pragma unroll
        for (int i = 0; i < 4; i++) {
            int r = 4 * i + r8;
            int y = __shfl_sync(0xffffffffu, ij.y, r);
            float4 v = *(float4*)(Dw + r * D_STRIDE + t8 * 4);
            if (r < vc) {
                float* op = out + (size_t)y * C + t8 * 4;
                asm volatile("red.global.add.v4.f32 [%0], {%1,%2,%3,%4};"
                             :: "l"(op), "f"(v.x), "f"(v.y), "f"(v.z), "f"(v.w)
                             : "memory");
            }
        }
        __syncwarp();   // D staging + A staging free before next iteration
    }
}

// ---------------------------------------------------------------------------
// Inputs: 0 in_feature f32 [N_VOX,32], 1 kernel f32 [27,32,32], 2 bias f32[32],
//         3 nbmap i32 [M,2], 4 nbsizes i32 [27]
// ---------------------------------------------------------------------------
extern "C" void kernel_launch(void* const* d_in, const int* in_sizes, int n_in,
                              void* d_out, int out_size) {
    const float* in_feature = (const float*)d_in[0];
    const float* weights    = (const float*)d_in[1];
    const float* bias       = (const float*)d_in[2];
    const int2*  nbmap      = (const int2*)d_in[3];
    float*       out        = (float*)d_out;

    int M  = in_sizes[3] / 2;
    int K3 = in_sizes[1] / (C * C);
    int P  = M / K3;

    int n4 = out_size / 4;
    init_bias_kernel<<<(n4 + 255) / 256, 256>>>(out, bias, n4);

    int blocksPerSeg = 32;
    spconv_hmma_kernel<<<K3 * blocksPerSeg, 256>>>(
        in_feature, weights, nbmap, out, P, blocksPerSeg);
}

// round 7
// speedup vs baseline: 4.2355x; 1.1520x over previous
#include <cuda_runtime.h>
#include <cuda_bf16.h>
#include <cstdint>

#define C 32
#define WARPS 8
#define STRIDE 40            // words per staged row (160B): phase-conflict-free
#define BUF_WORDS 640        // 16 rows * 40 words
#define WARP_WORDS 1280      // 2 buffers (A double-buffer; D overlaid on current A)

// ---------------------------------------------------------------------------
static __device__ __forceinline__ uint32_t smem_u32(const void* p) {
    uint32_t a;
    asm("{ .reg .u64 t; cvta.to.shared.u64 t, %1; cvt.u32.u64 %0, t; }"
        : "=r"(a) : "l"(p));
    return a;
}

// bf16 two-term split of a float2 -> (hi pair packed, lo pair packed)
static __device__ __forceinline__ uint2 split2(float x, float y) {
    __nv_bfloat162 h = __float22bfloat162_rn(make_float2(x, y));
    float hx = __bfloat162float(h.x);
    float hy = __bfloat162float(h.y);
    __nv_bfloat162 l = __float22bfloat162_rn(make_float2(x - hx, y - hy));
    uint2 r;
    r.x = *(uint32_t*)&h;
    r.y = *(uint32_t*)&l;
    return r;
}

static __device__ __forceinline__ void mma_bf16(float* d, const uint32_t* a,
                                                const uint32_t* b) {
    asm volatile(
        "mma.sync.aligned.m16n8k16.row.col.f32.bf16.bf16.f32 "
        "{%0,%1,%2,%3}, {%4,%5,%6,%7}, {%8,%9}, {%0,%1,%2,%3};"
        : "+f"(d[0]), "+f"(d[1]), "+f"(d[2]), "+f"(d[3])
        : "r"(a[0]), "r"(a[1]), "r"(a[2]), "r"(a[3]), "r"(b[0]), "r"(b[1]));
}

// ---------------------------------------------------------------------------
// Kernel 1: initialize output with bias
// ---------------------------------------------------------------------------
__global__ void init_bias_kernel(float* __restrict__ out,
                                 const float* __restrict__ bias, int n4) {
    int idx = blockIdx.x * blockDim.x + threadIdx.x;
    if (idx < n4) {
        const float4* b4 = (const float4*)bias;
        ((float4*)out)[idx] = b4[idx & 7];
    }
}

// ---------------------------------------------------------------------------
// Kernel 2: cp.async double-buffered gather -> split-bf16 HMMA -> staged scatter
// ---------------------------------------------------------------------------
__global__ __launch_bounds__(256, 3) void spconv_hmma_kernel(
    const float* __restrict__ in_feature,
    const float* __restrict__ weights,
    const int2* __restrict__ nbmap,
    float* __restrict__ out,
    int P, int blocksPerSeg)
{
    __shared__ uint32_t S[WARPS][WARP_WORDS];

    const int tid  = threadIdx.x;
    const int wid  = tid >> 5;
    const int lane = tid & 31;
    const int l4   = lane >> 2;   // 0..7
    const int lm4  = lane & 3;    // 0..3
    const int t8   = lane & 7;    // 16B chunk within 128B row
    const int r8   = lane >> 3;   // 0..3

    const int seg = blockIdx.x / blocksPerSeg;
    const int blk = blockIdx.x % blocksPerSeg;

    // ---- register-resident B fragments (hi & lo) for this segment ----
    const float* W = weights + seg * C * C;
    uint32_t Bh[4][2][2], Bl[4][2][2];
    #pragma unroll
    for (int n = 0; n < 4; n++) {
        #pragma unroll
        for (int kc = 0; kc < 2; kc++) {
            #pragma unroll
            for (int rr = 0; rr < 2; rr++) {
                int k0 = kc * 16 + lm4 * 2 + rr * 8;
                int ni = n * 8 + l4;
                uint2 s = split2(W[k0 * C + ni], W[(k0 + 1) * C + ni]);
                Bh[n][kc][rr] = s.x;
                Bl[n][kc][rr] = s.y;
            }
        }
    }

    // ---- per-warp contiguous pair range ----
    const int segStart = seg * P;
    const int segEnd   = segStart + P;
    const int warpsPerSeg = blocksPerSeg * WARPS;
    const int perWarp  = (P + warpsPerSeg - 1) / warpsPerSeg;
    const int wStart = segStart + (blk * WARPS + wid) * perWarp;
    const int wEnd   = min(wStart + perWarp, segEnd);
    if (wStart >= wEnd) return;   // no block-wide syncs below; safe

    const uint32_t sbase = smem_u32(&S[wid][0]);
    const int nIter = (wEnd - wStart + 15) >> 4;

    // load 16 pair records into lanes 0..15
    auto loadIJ = [&](int pB) -> int2 {
        int pc = min(pB + lane, segEnd - 1);
        return (lane < 16) ? nbmap[pc] : make_int2(0, 0);
    };
    // issue async gather of 16 fp32 rows into buffer bi
    auto gatherIssue = [&](int bi, int2 ij) {
        uint32_t abase = sbase + bi * (BUF_WORDS * 4);
        #pragma unroll
        for (int g = 0; g < 4; g++) {
            int r = 4 * g + r8;
            int x = __shfl_sync(0xffffffffu, ij.x, r);
            const char* src = (const char*)(in_feature + (size_t)x * C) + t8 * 16;
            uint32_t dst = abase + (r * STRIDE + t8 * 4) * 4;
            asm volatile("cp.async.cg.shared.global [%0], [%1], 16;"
                         :: "r"(dst), "l"(src) : "memory");
        }
    };

    // prologue
    int2 ij_cur = loadIJ(wStart);
    gatherIssue(0, ij_cur);
    asm volatile("cp.async.commit_group;" ::: "memory");

    for (int t = 0; t < nIter; t++) {
        const int pBase = wStart + t * 16;
        const int vc = min(16, wEnd - pBase);
        const int cur = t & 1;

        // prefetch next tile
        int2 ij_next = ij_cur;
        if (t + 1 < nIter) {
            ij_next = loadIJ(pBase + 16);
            gatherIssue(cur ^ 1, ij_next);
        }
        asm volatile("cp.async.commit_group;" ::: "memory");
        asm volatile("cp.async.wait_group 1;" ::: "memory");
        __syncwarp();

        // ---- load fp32 fragments from current buffer, split to hi/lo bf16 ----
        const float* Af = (const float*)&S[wid][cur * BUF_WORDS];
        uint32_t Ah[2][4], Al[2][4];
        #pragma unroll
        for (int kc = 0; kc < 2; kc++) {
            int kb = kc * 16 + 2 * lm4;
            float2 p0 = *(const float2*)(Af + l4 * STRIDE + kb);
            float2 p1 = *(const float2*)(Af + (l4 + 8) * STRIDE + kb);
            float2 p2 = *(const float2*)(Af + l4 * STRIDE + kb + 8);
            float2 p3 = *(const float2*)(Af + (l4 + 8) * STRIDE + kb + 8);
            uint2 s;
            s = split2(p0.x, p0.y); Ah[kc][0] = s.x; Al[kc][0] = s.y;
            s = split2(p1.x, p1.y); Ah[kc][1] = s.x; Al[kc][1] = s.y;
            s = split2(p2.x, p2.y); Ah[kc][2] = s.x; Al[kc][2] = s.y;
            s = split2(p3.x, p3.y); Ah[kc][3] = s.x; Al[kc][3] = s.y;
        }
        __syncwarp();   // all lanes done reading A before D overlays the buffer

        // ---- MMA (3-term split) + stage D rows into the current buffer ----
        float* Dw = (float*)&S[wid][cur * BUF_WORDS];
        #pragma unroll
        for (int n = 0; n < 4; n++) {
            float d[4] = {0.f, 0.f, 0.f, 0.f};
            #pragma unroll
            for (int kc = 0; kc < 2; kc++) {
                mma_bf16(d, Ah[kc], Bh[n][kc]);
                mma_bf16(d, Ah[kc], Bl[n][kc]);
                mma_bf16(d, Al[kc], Bh[n][kc]);
            }
            *(float2*)(Dw + l4 * STRIDE + n * 8 + lm4 * 2)       = make_float2(d[0], d[1]);
            *(float2*)(Dw + (l4 + 8) * STRIDE + n * 8 + lm4 * 2) = make_float2(d[2], d[3]);
        }
        __syncwarp();

        // ---- scatter: 4 red instructions, each = 4 complete 128B rows ----
        #pragma unroll
        for (int i = 0; i < 4; i++) {
            int r = 4 * i + r8;
            int y = __shfl_sync(0xffffffffu, ij_cur.y, r);
            float4 v = *(float4*)(Dw + r * STRIDE + t8 * 4);
            if (r < vc) {
                float* op = out + (size_t)y * C + t8 * 4;
                asm volatile("red.global.add.v4.f32 [%0], {%1,%2,%3,%4};"
                             :: "l"(op), "f"(v.x), "f"(v.y), "f"(v.z), "f"(v.w)
                             : "memory");
            }
        }
        __syncwarp();   // D reads done before next iter's cp.async reuses buffer

        ij_cur = ij_next;
    }
}

// ---------------------------------------------------------------------------
// Inputs: 0 in_feature f32 [N_VOX,32], 1 kernel f32 [27,32,32], 2 bias f32[32],
//         3 nbmap i32 [M,2], 4 nbsizes i32 [27]
// ---------------------------------------------------------------------------
extern "C" void kernel_launch(void* const* d_in, const int* in_sizes, int n_in,
                              void* d_out, int out_size) {
    const float* in_feature = (const float*)d_in[0];
    const float* weights    = (const float*)d_in[1];
    const float* bias       = (const float*)d_in[2];
    const int2*  nbmap      = (const int2*)d_in[3];
    float*       out        = (float*)d_out;

    int M  = in_sizes[3] / 2;
    int K3 = in_sizes[1] / (C * C);
    int P  = M / K3;

    int n4 = out_size / 4;
    init_bias_kernel<<<(n4 + 255) / 256, 256>>>(out, bias, n4);

    int blocksPerSeg = 32;
    spconv_hmma_kernel<<<K3 * blocksPerSeg, 256>>>(
        in_feature, weights, nbmap, out, P, blocksPerSeg);
}

// round 8
// speedup vs baseline: 4.5471x; 1.0736x over previous
#include <cuda_runtime.h>
#include <cuda_bf16.h>
#include <cstdint>

#define C 32
#define WARPS 8
#define STRIDE 40            // words per staged row (160B): phase-conflict-free
#define BUF_WORDS 640        // 16 rows * 40 words
#define WARP_WORDS 1280      // 2 buffers (A double-buffer; D overlaid on current A)

// ---------------------------------------------------------------------------
static __device__ __forceinline__ uint32_t smem_u32(const void* p) {
    uint32_t a;
    asm("{ .reg .u64 t; cvta.to.shared.u64 t, %1; cvt.u32.u64 %0, t; }"
        : "=r"(a) : "l"(p));
    return a;
}

// bf16 two-term split of a float2 -> (hi pair packed, lo pair packed)
static __device__ __forceinline__ uint2 split2(float x, float y) {
    __nv_bfloat162 h = __float22bfloat162_rn(make_float2(x, y));
    float hx = __bfloat162float(h.x);
    float hy = __bfloat162float(h.y);
    __nv_bfloat162 l = __float22bfloat162_rn(make_float2(x - hx, y - hy));
    uint2 r;
    r.x = *(uint32_t*)&h;
    r.y = *(uint32_t*)&l;
    return r;
}

static __device__ __forceinline__ void mma_bf16(float* d, const uint32_t* a,
                                                const uint32_t* b) {
    asm volatile(
        "mma.sync.aligned.m16n8k16.row.col.f32.bf16.bf16.f32 "
        "{%0,%1,%2,%3}, {%4,%5,%6,%7}, {%8,%9}, {%0,%1,%2,%3};"
        : "+f"(d[0]), "+f"(d[1]), "+f"(d[2]), "+f"(d[3])
        : "r"(a[0]), "r"(a[1]), "r"(a[2]), "r"(a[3]), "r"(b[0]), "r"(b[1]));
}

// ---------------------------------------------------------------------------
// Kernel 1: initialize output with bias
// ---------------------------------------------------------------------------
__global__ void init_bias_kernel(float* __restrict__ out,
                                 const float* __restrict__ bias, int n4) {
    int idx = blockIdx.x * blockDim.x + threadIdx.x;
    if (idx < n4) {
        const float4* b4 = (const float4*)bias;
        ((float4*)out)[idx] = b4[idx & 7];
    }
}

// ---------------------------------------------------------------------------
// Kernel 2: cp.async double-buffered gather (+2-ahead index prefetch)
//           -> split-bf16 HMMA -> smem-staged full-row scatter-add
// ---------------------------------------------------------------------------
__global__ __launch_bounds__(256, 3) void spconv_hmma_kernel(
    const float* __restrict__ in_feature,
    const float* __restrict__ weights,
    const int2* __restrict__ nbmap,
    float* __restrict__ out,
    int P, int blocksPerSeg)
{
    __shared__ uint32_t S[WARPS][WARP_WORDS];

    const int tid  = threadIdx.x;
    const int wid  = tid >> 5;
    const int lane = tid & 31;
    const int l4   = lane >> 2;   // 0..7
    const int lm4  = lane & 3;    // 0..3
    const int t8   = lane & 7;    // 16B chunk within 128B row
    const int r8   = lane >> 3;   // 0..3

    const int seg = blockIdx.x / blocksPerSeg;
    const int blk = blockIdx.x % blocksPerSeg;

    // ---- register-resident B fragments (hi & lo) for this segment ----
    const float* W = weights + seg * C * C;
    uint32_t Bh[4][2][2], Bl[4][2][2];
    #pragma unroll
    for (int n = 0; n < 4; n++) {
        #pragma unroll
        for (int kc = 0; kc < 2; kc++) {
            #pragma unroll
            for (int rr = 0; rr < 2; rr++) {
                int k0 = kc * 16 + lm4 * 2 + rr * 8;
                int ni = n * 8 + l4;
                uint2 s = split2(W[k0 * C + ni], W[(k0 + 1) * C + ni]);
                Bh[n][kc][rr] = s.x;
                Bl[n][kc][rr] = s.y;
            }
        }
    }

    // ---- per-warp contiguous pair range ----
    const int segStart = seg * P;
    const int segEnd   = segStart + P;
    const int warpsPerSeg = blocksPerSeg * WARPS;
    const int perWarp  = (P + warpsPerSeg - 1) / warpsPerSeg;
    const int wStart = segStart + (blk * WARPS + wid) * perWarp;
    const int wEnd   = min(wStart + perWarp, segEnd);
    if (wStart >= wEnd) return;   // no block-wide syncs below; safe

    const uint32_t sbase = smem_u32(&S[wid][0]);
    const int nIter = (wEnd - wStart + 15) >> 4;

    // load 16 pair records into lanes 0..15
    auto loadIJ = [&](int pB) -> int2 {
        int pc = min(pB + lane, segEnd - 1);
        return (lane < 16) ? nbmap[pc] : make_int2(0, 0);
    };
    // issue async gather of 16 fp32 rows into buffer bi
    auto gatherIssue = [&](int bi, int2 ij) {
        uint32_t abase = sbase + bi * (BUF_WORDS * 4);
        #pragma unroll
        for (int g = 0; g < 4; g++) {
            int r = 4 * g + r8;
            int x = __shfl_sync(0xffffffffu, ij.x, r);
            const char* src = (const char*)(in_feature + (size_t)x * C) + t8 * 16;
            uint32_t dst = abase + (r * STRIDE + t8 * 4) * 4;
            asm volatile("cp.async.cg.shared.global [%0], [%1], 16;"
                         :: "r"(dst), "l"(src) : "memory");
        }
    };

    // ---- prologue: indices 2 ahead, gather 1 ahead ----
    int2 ij_cur = loadIJ(wStart);          // only exposed index-LDG stall
    gatherIssue(0, ij_cur);
    asm volatile("cp.async.commit_group;" ::: "memory");
    int2 ij_next = (nIter > 1) ? loadIJ(wStart + 16) : ij_cur;

    for (int t = 0; t < nIter; t++) {
        const int pBase = wStart + t * 16;
        const int vc = min(16, wEnd - pBase);
        const int cur = t & 1;

        // issue gather for t+1 (indices already register-resident: no stall)
        if (t + 1 < nIter) gatherIssue(cur ^ 1, ij_next);
        asm volatile("cp.async.commit_group;" ::: "memory");

        // issue index load for t+2 (latency hidden across this iteration)
        int2 ij_next2 = (t + 2 < nIter) ? loadIJ(pBase + 32) : ij_next;

        asm volatile("cp.async.wait_group 1;" ::: "memory");
        __syncwarp();

        // ---- load fp32 fragments from current buffer, split to hi/lo bf16 ----
        const float* Af = (const float*)&S[wid][cur * BUF_WORDS];
        uint32_t Ah[2][4], Al[2][4];
        #pragma unroll
        for (int kc = 0; kc < 2; kc++) {
            int kb = kc * 16 + 2 * lm4;
            float2 p0 = *(const float2*)(Af + l4 * STRIDE + kb);
            float2 p1 = *(const float2*)(Af + (l4 + 8) * STRIDE + kb);
            float2 p2 = *(const float2*)(Af + l4 * STRIDE + kb + 8);
            float2 p3 = *(const float2*)(Af + (l4 + 8) * STRIDE + kb + 8);
            uint2 s;
            s = split2(p0.x, p0.y); Ah[kc][0] = s.x; Al[kc][0] = s.y;
            s = split2(p1.x, p1.y); Ah[kc][1] = s.x; Al[kc][1] = s.y;
            s = split2(p2.x, p2.y); Ah[kc][2] = s.x; Al[kc][2] = s.y;
            s = split2(p3.x, p3.y); Ah[kc][3] = s.x; Al[kc][3] = s.y;
        }
        __syncwarp();   // all lanes done reading A before D overlays the buffer

        // ---- MMA (3-term split) + stage D rows into the current buffer ----
        float* Dw = (float*)&S[wid][cur * BUF_WORDS];
        #pragma unroll
        for (int n = 0; n < 4; n++) {
            float d[4] = {0.f, 0.f, 0.f, 0.f};
            #pragma unroll
            for (int kc = 0; kc < 2; kc++) {
                mma_bf16(d, Ah[kc], Bh[n][kc]);
                mma_bf16(d, Ah[kc], Bl[n][kc]);
                mma_bf16(d, Al[kc], Bh[n][kc]);
            }
            *(float2*)(Dw + l4 * STRIDE + n * 8 + lm4 * 2)       = make_float2(d[0], d[1]);
            *(float2*)(Dw + (l4 + 8) * STRIDE + n * 8 + lm4 * 2) = make_float2(d[2], d[3]);
        }
        __syncwarp();

        // ---- scatter: 4 red instructions, each = 4 complete 128B rows ----
        #pragma unroll
        for (int i = 0; i < 4; i++) {
            int r = 4 * i + r8;
            int y = __shfl_sync(0xffffffffu, ij_cur.y, r);
            float4 v = *(float4*)(Dw + r * STRIDE + t8 * 4);
            if (r < vc) {
                float* op = out + (size_t)y * C + t8 * 4;
                asm volatile("red.global.add.v4.f32 [%0], {%1,%2,%3,%4};"
                             :: "l"(op), "f"(v.x), "f"(v.y), "f"(v.z), "f"(v.w)
                             : "memory");
            }
        }
        __syncwarp();   // D reads done before next iter's cp.async reuses buffer

        ij_cur = ij_next;
        ij_next = ij_next2;
    }
}

// ---------------------------------------------------------------------------
// Inputs: 0 in_feature f32 [N_VOX,32], 1 kernel f32 [27,32,32], 2 bias f32[32],
//         3 nbmap i32 [M,2], 4 nbsizes i32 [27]
// ---------------------------------------------------------------------------
extern "C" void kernel_launch(void* const* d_in, const int* in_sizes, int n_in,
                              void* d_out, int out_size) {
    const float* in_feature = (const float*)d_in[0];
    const float* weights    = (const float*)d_in[1];
    const float* bias       = (const float*)d_in[2];
    const int2*  nbmap      = (const int2*)d_in[3];
    float*       out        = (float*)d_out;

    int M  = in_sizes[3] / 2;
    int K3 = in_sizes[1] / (C * C);
    int P  = M / K3;

    int n4 = out_size / 4;
    init_bias_kernel<<<(n4 + 255) / 256, 256>>>(out, bias, n4);

    int blocksPerSeg = 32;
    spconv_hmma_kernel<<<K3 * blocksPerSeg, 256>>>(
        in_feature, weights, nbmap, out, P, blocksPerSeg);
}

// round 10
// speedup vs baseline: 4.6000x; 1.0116x over previous
#include <cuda_runtime.h>
#include <cuda_bf16.h>
#include <cstdint>

#define C 32
#define WARPS 8
#define STRIDE 40            // words per staged row (160B): conflict-free phases
#define ROWS_T 32            // pairs per warp-iteration
#define BUF_WORDS (ROWS_T * STRIDE)       // 1280 words = 5KB
#define WARP_WORDS (2 * BUF_WORDS)        // double buffer (D overlays current A)
#define SMEM_BYTES (WARPS * WARP_WORDS * 4)  // 80KB

// ---------------------------------------------------------------------------
static __device__ __forceinline__ uint32_t smem_u32(const void* p) {
    uint32_t a;
    asm("{ .reg .u64 t; cvta.to.shared.u64 t, %1; cvt.u32.u64 %0, t; }"
        : "=r"(a) : "l"(p));
    return a;
}

// bf16 two-term split of a float2 -> (hi pair packed, lo pair packed)
static __device__ __forceinline__ uint2 split2(float x, float y) {
    __nv_bfloat162 h = __float22bfloat162_rn(make_float2(x, y));
    float hx = __bfloat162float(h.x);
    float hy = __bfloat162float(h.y);
    __nv_bfloat162 l = __float22bfloat162_rn(make_float2(x - hx, y - hy));
    uint2 r;
    r.x = *(uint32_t*)&h;
    r.y = *(uint32_t*)&l;
    return r;
}

static __device__ __forceinline__ void mma_bf16(float* d, const uint32_t* a,
                                                const uint32_t* b) {
    asm volatile(
        "mma.sync.aligned.m16n8k16.row.col.f32.bf16.bf16.f32 "
        "{%0,%1,%2,%3}, {%4,%5,%6,%7}, {%8,%9}, {%0,%1,%2,%3};"
        : "+f"(d[0]), "+f"(d[1]), "+f"(d[2]), "+f"(d[3])
        : "r"(a[0]), "r"(a[1]), "r"(a[2]), "r"(a[3]), "r"(b[0]), "r"(b[1]));
}

// ---------------------------------------------------------------------------
// Kernel 1: initialize output with bias
// ---------------------------------------------------------------------------
__global__ void init_bias_kernel(float* __restrict__ out,
                                 const float* __restrict__ bias, int n4) {
    int idx = blockIdx.x * blockDim.x + threadIdx.x;
    if (idx < n4) {
        const float4* b4 = (const float4*)bias;
        ((float4*)out)[idx] = b4[idx & 7];
    }
}

// ---------------------------------------------------------------------------
// Kernel 2: 32-pair tiles, cp.async double-buffered gather (+2-ahead index
// prefetch) -> split-bf16 HMMA (2 m-tiles) -> smem-staged full-row scatter
// ---------------------------------------------------------------------------
__global__ __launch_bounds__(256, 2) void spconv_hmma_kernel(
    const float* __restrict__ in_feature,
    const float* __restrict__ weights,
    const int2* __restrict__ nbmap,
    float* __restrict__ out,
    int P, int blocksPerSeg)
{
    extern __shared__ uint32_t S[];

    const int tid  = threadIdx.x;
    const int wid  = tid >> 5;
    const int lane = tid & 31;
    const int l4   = lane >> 2;   // 0..7
    const int lm4  = lane & 3;    // 0..3
    const int t8   = lane & 7;    // 16B chunk within 128B row
    const int r8   = lane >> 3;   // 0..3

    const int seg = blockIdx.x / blocksPerSeg;
    const int blk = blockIdx.x % blocksPerSeg;

    // ---- register-resident B fragments (hi & lo) for this segment ----
    const float* W = weights + seg * C * C;
    uint32_t Bh[4][2][2], Bl[4][2][2];
    #pragma unroll
    for (int n = 0; n < 4; n++) {
        #pragma unroll
        for (int kc = 0; kc < 2; kc++) {
            #pragma unroll
            for (int rr = 0; rr < 2; rr++) {
                int k0 = kc * 16 + lm4 * 2 + rr * 8;
                int ni = n * 8 + l4;
                uint2 s = split2(W[k0 * C + ni], W[(k0 + 1) * C + ni]);
                Bh[n][kc][rr] = s.x;
                Bl[n][kc][rr] = s.y;
            }
        }
    }

    // ---- per-warp contiguous pair range ----
    const int segStart = seg * P;
    const int segEnd   = segStart + P;
    const int warpsPerSeg = blocksPerSeg * WARPS;
    const int perWarp  = (P + warpsPerSeg - 1) / warpsPerSeg;
    const int wStart = segStart + (blk * WARPS + wid) * perWarp;
    const int wEnd   = min(wStart + perWarp, segEnd);
    if (wStart >= wEnd) return;   // no block-wide syncs below; safe

    uint32_t* Swarp = S + wid * WARP_WORDS;
    const uint32_t sbase = smem_u32(Swarp);
    const int nIter = (wEnd - wStart + ROWS_T - 1) / ROWS_T;

    // load 32 pair records (one per lane)
    auto loadIJ = [&](int pB) -> int2 {
        int pc = min(pB + lane, segEnd - 1);
        return nbmap[pc];
    };
    // issue async gather of 32 fp32 rows into buffer bi
    auto gatherIssue = [&](int bi, int2 ij) {
        uint32_t abase = sbase + bi * (BUF_WORDS * 4);
        #pragma unroll
        for (int g = 0; g < 8; g++) {
            int r = 4 * g + r8;
            int x = __shfl_sync(0xffffffffu, ij.x, r);
            const char* src = (const char*)(in_feature + (size_t)x * C) + t8 * 16;
            uint32_t dst = abase + (r * STRIDE + t8 * 4) * 4;
            asm volatile("cp.async.cg.shared.global [%0], [%1], 16;"
                         :: "r"(dst), "l"(src) : "memory");
        }
    };

    // ---- prologue: indices 2 ahead, gather 1 ahead ----
    int2 ij_cur = loadIJ(wStart);
    gatherIssue(0, ij_cur);
    asm volatile("cp.async.commit_group;" ::: "memory");
    int2 ij_next = (nIter > 1) ? loadIJ(wStart + ROWS_T) : ij_cur;

    for (int t = 0; t < nIter; t++) {
        const int pBase = wStart + t * ROWS_T;
        const int vc = min(ROWS_T, wEnd - pBase);
        const int cur = t & 1;

        // issue gather for t+1 (indices already register-resident)
        if (t + 1 < nIter) gatherIssue(cur ^ 1, ij_next);
        asm volatile("cp.async.commit_group;" ::: "memory");

        // issue index load for t+2 (latency hidden across this iteration)
        int2 ij_next2 = (t + 2 < nIter) ? loadIJ(pBase + 2 * ROWS_T) : ij_next;

        asm volatile("cp.async.wait_group 1;" ::: "memory");
        __syncwarp();

        // ---- load fp32 fragments (2 m-tiles), split to hi/lo bf16 ----
        const float* Af = (const float*)(Swarp + cur * BUF_WORDS);
        uint32_t Ah[2][2][4], Al[2][2][4];
        #pragma unroll
        for (int m = 0; m < 2; m++) {
            #pragma unroll
            for (int kc = 0; kc < 2; kc++) {
                int kb = kc * 16 + 2 * lm4;
                int r0 = 16 * m + l4;
                float2 p0 = *(const float2*)(Af + r0 * STRIDE + kb);
                float2 p1 = *(const float2*)(Af + (r0 + 8) * STRIDE + kb);
                float2 p2 = *(const float2*)(Af + r0 * STRIDE + kb + 8);
                float2 p3 = *(const float2*)(Af + (r0 + 8) * STRIDE + kb + 8);
                uint2 s;
                s = split2(p0.x, p0.y); Ah[m][kc][0] = s.x; Al[m][kc][0] = s.y;
                s = split2(p1.x, p1.y); Ah[m][kc][1] = s.x; Al[m][kc][1] = s.y;
                s = split2(p2.x, p2.y); Ah[m][kc][2] = s.x; Al[m][kc][2] = s.y;
                s = split2(p3.x, p3.y); Ah[m][kc][3] = s.x; Al[m][kc][3] = s.y;
            }
        }
        __syncwarp();   // all lanes done reading A before D overlays the buffer

        // ---- MMA (3-term split) + stage D rows into the current buffer ----
        float* Dw = (float*)(Swarp + cur * BUF_WORDS);
        #pragma unroll
        for (int n = 0; n < 4; n++) {
            #pragma unroll
            for (int m = 0; m < 2; m++) {
                float d[4] = {0.f, 0.f, 0.f, 0.f};
                #pragma unroll
                for (int kc = 0; kc < 2; kc++) {
                    mma_bf16(d, Ah[m][kc], Bh[n][kc]);
                    mma_bf16(d, Ah[m][kc], Bl[n][kc]);
                    mma_bf16(d, Al[m][kc], Bh[n][kc]);
                }
                int r0 = 16 * m + l4;
                *(float2*)(Dw + r0 * STRIDE + n * 8 + lm4 * 2)       = make_float2(d[0], d[1]);
                *(float2*)(Dw + (r0 + 8) * STRIDE + n * 8 + lm4 * 2) = make_float2(d[2], d[3]);
            }
        }
        __syncwarp();

        // ---- scatter: 8 red instructions, each = 4 complete 128B rows ----
        #pragma unroll
        for (int i = 0; i < 8; i++) {
            int r = 4 * i + r8;
            int y = __shfl_sync(0xffffffffu, ij_cur.y, r);
            float4 v = *(float4*)(Dw + r * STRIDE + t8 * 4);
            if (r < vc) {
                float* op = out + (size_t)y * C + t8 * 4;
                asm volatile("red.global.add.v4.f32 [%0], {%1,%2,%3,%4};"
                             :: "l"(op), "f"(v.x), "f"(v.y), "f"(v.z), "f"(v.w)
                             : "memory");
            }
        }
        __syncwarp();   // D reads done before next iter's cp.async reuses buffer

        ij_cur = ij_next;
        ij_next = ij_next2;
    }
}

// ---------------------------------------------------------------------------
// Inputs: 0 in_feature f32 [N_VOX,32], 1 kernel f32 [27,32,32], 2 bias f32[32],
//         3 nbmap i32 [M,2], 4 nbsizes i32 [27]
// ---------------------------------------------------------------------------
extern "C" void kernel_launch(void* const* d_in, const int* in_sizes, int n_in,
                              void* d_out, int out_size) {
    const float* in_feature = (const float*)d_in[0];
    const float* weights    = (const float*)d_in[1];
    const float* bias       = (const float*)d_in[2];
    const int2*  nbmap      = (const int2*)d_in[3];
    float*       out        = (float*)d_out;

    int M  = in_sizes[3] / 2;
    int K3 = in_sizes[1] / (C * C);
    int P  = M / K3;

    int n4 = out_size / 4;
    init_bias_kernel<<<(n4 + 255) / 256, 256>>>(out, bias, n4);

    // dynamic smem > 48KB requires opting in (attribute set, not an allocation)
    static int smem_set = 0;
    if (!smem_set) {
        cudaFuncSetAttribute(spconv_hmma_kernel,
                             cudaFuncAttributeMaxDynamicSharedMemorySize,
                             SMEM_BYTES);
        smem_set = 1;
    }

    int blocksPerSeg = 32;
    spconv_hmma_kernel<<<K3 * blocksPerSeg, 256, SMEM_BYTES>>>(
        in_feature, weights, nbmap, out, P, blocksPerSeg);
}

// round 11
// speedup vs baseline: 4.7335x; 1.0290x over previous
#include <cuda_runtime.h>
#include <cuda_bf16.h>
#include <cstdint>

#define C 32
#define WARPS 8
#define STRIDE 40            // words per staged row (160B): conflict-free half-warp phases
#define ROWS_T 32            // pairs per warp-iteration
#define BUF_WORDS (ROWS_T * STRIDE)       // 1280 words = 5KB
#define WARP_WORDS (2 * BUF_WORDS)        // double buffer (gather only; no D staging)
#define SMEM_BYTES (WARPS * WARP_WORDS * 4)  // 80KB

// ---------------------------------------------------------------------------
static __device__ __forceinline__ uint32_t smem_u32(const void* p) {
    uint32_t a;
    asm("{ .reg .u64 t; cvta.to.shared.u64 t, %1; cvt.u32.u64 %0, t; }"
        : "=r"(a) : "l"(p));
    return a;
}

// bf16 two-term split of a float2 -> (hi pair packed, lo pair packed)
static __device__ __forceinline__ uint2 split2(float x, float y) {
    __nv_bfloat162 h = __float22bfloat162_rn(make_float2(x, y));
    float hx = __bfloat162float(h.x);
    float hy = __bfloat162float(h.y);
    __nv_bfloat162 l = __float22bfloat162_rn(make_float2(x - hx, y - hy));
    uint2 r;
    r.x = *(uint32_t*)&h;
    r.y = *(uint32_t*)&l;
    return r;
}

static __device__ __forceinline__ void mma_bf16(float* d, const uint32_t* a,
                                                const uint32_t* b) {
    asm volatile(
        "mma.sync.aligned.m16n8k16.row.col.f32.bf16.bf16.f32 "
        "{%0,%1,%2,%3}, {%4,%5,%6,%7}, {%8,%9}, {%0,%1,%2,%3};"
        : "+f"(d[0]), "+f"(d[1]), "+f"(d[2]), "+f"(d[3])
        : "r"(a[0]), "r"(a[1]), "r"(a[2]), "r"(a[3]), "r"(b[0]), "r"(b[1]));
}

// ---------------------------------------------------------------------------
// Kernel 1: initialize output with bias
// ---------------------------------------------------------------------------
__global__ void init_bias_kernel(float* __restrict__ out,
                                 const float* __restrict__ bias, int n4) {
    int idx = blockIdx.x * blockDim.x + threadIdx.x;
    if (idx < n4) {
        const float4* b4 = (const float4*)bias;
        ((float4*)out)[idx] = b4[idx & 7];
    }
}

// ---------------------------------------------------------------------------
// Kernel 2: transposed GEMM — W is the A operand (M=32 couts, permuted rows),
// gathered input rows are the B operand (N=pairs). Lane accumulators hold 4
// consecutive couts per pair -> red.global.add.v4 straight from registers.
// cp.async double-buffered gather + 2-ahead index prefetch retained.
// ---------------------------------------------------------------------------
__global__ __launch_bounds__(256, 2) void spconv_hmma_kernel(
    const float* __restrict__ in_feature,
    const float* __restrict__ weights,
    const int2* __restrict__ nbmap,
    float* __restrict__ out,
    int P, int blocksPerSeg)
{
    extern __shared__ uint32_t S[];

    const int tid  = threadIdx.x;
    const int wid  = tid >> 5;
    const int lane = tid & 31;
    const int l4   = lane >> 2;   // 0..7
    const int lm4  = lane & 3;    // 0..3
    const int t8   = lane & 7;    // 16B chunk within 128B row
    const int r8   = lane >> 3;   // 0..3

    const int seg = blockIdx.x / blocksPerSeg;
    const int blk = blockIdx.x % blocksPerSeg;

    // ---- register-resident W fragments as MMA A-operand (hi & lo) ----
    // A-frag m16n8k16 row-major: a0=(row l4, k=2lm4..+1), a1=(row l4+8, same k),
    // a2=(row l4, k+8), a3=(row l4+8, k+8).
    // Row->cout permutation: m-tile m, row r<8 -> cout 4r+2m ; row r>=8 -> 4(r-8)+2m+1
    // => lane's couts {4l4, 4l4+1, 4l4+2, 4l4+3} across (m,reg) — consecutive.
    const float* W = weights + seg * C * C;   // W[cin][cout]
    uint32_t Wh[2][2][4], Wl[2][2][4];
    #pragma unroll
    for (int m = 0; m < 2; m++) {
        #pragma unroll
        for (int kc = 0; kc < 2; kc++) {
            #pragma unroll
            for (int r = 0; r < 4; r++) {
                int cout = 4 * l4 + 2 * m + (r & 1);        // row_sel = r&1
                int kk   = 2 * lm4 + 16 * kc + ((r >> 1) * 8);
                uint2 s = split2(W[kk * C + cout], W[(kk + 1) * C + cout]);
                Wh[m][kc][r] = s.x;
                Wl[m][kc][r] = s.y;
            }
        }
    }

    // ---- per-warp contiguous pair range ----
    const int segStart = seg * P;
    const int segEnd   = segStart + P;
    const int warpsPerSeg = blocksPerSeg * WARPS;
    const int perWarp  = (P + warpsPerSeg - 1) / warpsPerSeg;
    const int wStart = segStart + (blk * WARPS + wid) * perWarp;
    const int wEnd   = min(wStart + perWarp, segEnd);
    if (wStart >= wEnd) return;   // no block-wide syncs below; safe

    uint32_t* Swarp = S + wid * WARP_WORDS;
    const uint32_t sbase = smem_u32(Swarp);
    const int nIter = (wEnd - wStart + ROWS_T - 1) / ROWS_T;

    // load 32 pair records (one per lane)
    auto loadIJ = [&](int pB) -> int2 {
        int pc = min(pB + lane, segEnd - 1);
        return nbmap[pc];
    };
    // issue async gather of 32 fp32 rows into buffer bi
    auto gatherIssue = [&](int bi, int2 ij) {
        uint32_t abase = sbase + bi * (BUF_WORDS * 4);
        #pragma unroll
        for (int g = 0; g < 8; g++) {
            int r = 4 * g + r8;
            int x = __shfl_sync(0xffffffffu, ij.x, r);
            const char* src = (const char*)(in_feature + (size_t)x * C) + t8 * 16;
            uint32_t dst = abase + (r * STRIDE + t8 * 4) * 4;
            asm volatile("cp.async.cg.shared.global [%0], [%1], 16;"
                         :: "r"(dst), "l"(src) : "memory");
        }
    };

    // ---- prologue: indices 2 ahead, gather 1 ahead ----
    int2 ij_cur = loadIJ(wStart);
    gatherIssue(0, ij_cur);
    asm volatile("cp.async.commit_group;" ::: "memory");
    int2 ij_next = (nIter > 1) ? loadIJ(wStart + ROWS_T) : ij_cur;

    for (int t = 0; t < nIter; t++) {
        const int pBase = wStart + t * ROWS_T;
        const int vc = min(ROWS_T, wEnd - pBase);
        const int cur = t & 1;

        // issue gather for t+1 (indices already register-resident)
        if (t + 1 < nIter) gatherIssue(cur ^ 1, ij_next);
        asm volatile("cp.async.commit_group;" ::: "memory");

        // issue index load for t+2 (latency hidden across this iteration)
        int2 ij_next2 = (t + 2 < nIter) ? loadIJ(pBase + 2 * ROWS_T) : ij_next;

        asm volatile("cp.async.wait_group 1;" ::: "memory");
        __syncwarp();

        const float* Af = (const float*)(Swarp + cur * BUF_WORDS);

        // ---- per n-tile (8 pairs): B-frag load+split, MMA, direct RED ----
        #pragma unroll
        for (int n = 0; n < 4; n++) {
            // B frag (col-major): col = l4 -> pair row 8n+l4 in the buffer;
            // b0: k=2lm4,+1 ; b1: k+8 ; per kc add 16.
            uint32_t gh[2][2], gl[2][2];
            #pragma unroll
            for (int kc = 0; kc < 2; kc++) {
                const float* rp = Af + (8 * n + l4) * STRIDE + 16 * kc + 2 * lm4;
                float2 q0 = *(const float2*)(rp);
                float2 q1 = *(const float2*)(rp + 8);
                uint2 s;
                s = split2(q0.x, q0.y); gh[kc][0] = s.x; gl[kc][0] = s.y;
                s = split2(q1.x, q1.y); gh[kc][1] = s.x; gl[kc][1] = s.y;
            }

            float d0[4] = {0.f, 0.f, 0.f, 0.f};   // m-tile 0: couts 4l4, 4l4+1
            float d1[4] = {0.f, 0.f, 0.f, 0.f};   // m-tile 1: couts 4l4+2, 4l4+3
            #pragma unroll
            for (int kc = 0; kc < 2; kc++) {
                mma_bf16(d0, Wh[0][kc], gh[kc]);
                mma_bf16(d0, Wh[0][kc], gl[kc]);
                mma_bf16(d0, Wl[0][kc], gh[kc]);
                mma_bf16(d1, Wh[1][kc], gh[kc]);
                mma_bf16(d1, Wh[1][kc], gl[kc]);
                mma_bf16(d1, Wl[1][kc], gh[kc]);
            }

            // epilogue: D col c=2lm4+parity is pair n*8+c; lane holds couts
            // {4l4..4l4+3} = {d0[par], d0[2+par], d1[par], d1[2+par]}
            #pragma unroll
            for (int par = 0; par < 2; par++) {
                int p = n * 8 + 2 * lm4 + par;
                int y = __shfl_sync(0xffffffffu, ij_cur.y, p);
                if (p < vc) {
                    float* op = out + (size_t)y * C + 4 * l4;
                    asm volatile("red.global.add.v4.f32 [%0], {%1,%2,%3,%4};"
                                 :: "l"(op),
                                    "f"(d0[par]), "f"(d0[2 + par]),
                                    "f"(d1[par]), "f"(d1[2 + par])
                                 : "memory");
                }
            }
        }

        ij_cur = ij_next;
        ij_next = ij_next2;
    }
}

// ---------------------------------------------------------------------------
// Inputs: 0 in_feature f32 [N_VOX,32], 1 kernel f32 [27,32,32], 2 bias f32[32],
//         3 nbmap i32 [M,2], 4 nbsizes i32 [27]
// ---------------------------------------------------------------------------
extern "C" void kernel_launch(void* const* d_in, const int* in_sizes, int n_in,
                              void* d_out, int out_size) {
    const float* in_feature = (const float*)d_in[0];
    const float* weights    = (const float*)d_in[1];
    const float* bias       = (const float*)d_in[2];
    const int2*  nbmap      = (const int2*)d_in[3];
    float*       out        = (float*)d_out;

    int M  = in_sizes[3] / 2;
    int K3 = in_sizes[1] / (C * C);
    int P  = M / K3;

    int n4 = out_size / 4;
    init_bias_kernel<<<(n4 + 255) / 256, 256>>>(out, bias, n4);

    // dynamic smem > 48KB requires opting in (attribute set, not an allocation)
    static int smem_set = 0;
    if (!smem_set) {
        cudaFuncSetAttribute(spconv_hmma_kernel,
                             cudaFuncAttributeMaxDynamicSharedMemorySize,
                             SMEM_BYTES);
        smem_set = 1;
    }

    int blocksPerSeg = 32;
    spconv_hmma_kernel<<<K3 * blocksPerSeg, 256, SMEM_BYTES>>>(
        in_feature, weights, nbmap, out, P, blocksPerSeg);
}